// round 1
// baseline (speedup 1.0000x reference)
#include <cuda_runtime.h>

#define BB 16
#define NN 2048
#define DD 128

// scratch (static device allocations are allowed)
__device__ float g_seq[(size_t)BB * NN * DD];
__device__ float g_q[BB * NN];
__device__ float g_k[BB * NN];
__device__ float g_rden[BB * NN];

// ---------------------------------------------------------------------------
// Kernel 1: seq_fts = x @ W^T + b_emb ;  q = seq_fts.w_q + b_q ; k likewise
// 128 threads/block, 32 rows/block. W staged transposed in smem (pad 129).
// ---------------------------------------------------------------------------
__global__ __launch_bounds__(128) void k_emb(
    const float* __restrict__ x, const float* __restrict__ W,
    const float* __restrict__ b_emb,
    const float* __restrict__ w_q, const float* __restrict__ b_q,
    const float* __restrict__ w_k, const float* __restrict__ b_k)
{
    __shared__ float x_s[32][128];
    __shared__ float wt_s[32][129];
    __shared__ float red_q[4][32];
    __shared__ float red_k[4][32];

    const int tid  = threadIdx.x;
    const int lane = tid & 31;
    const int warp = tid >> 5;
    const size_t row0 = (size_t)blockIdx.x * 32;

    #pragma unroll 4
    for (int r = 0; r < 32; r++)
        x_s[r][tid] = x[(row0 + r) * DD + tid];

    float acc[32];
    #pragma unroll
    for (int r = 0; r < 32; r++) acc[r] = 0.f;

    const int i_sub = tid & 31;
    const int o_sub = tid >> 5;

    for (int chunk = 0; chunk < 4; chunk++) {
        __syncthreads();
        // load W[o][chunk*32 + i] transposed into wt_s[i][o], coalesced on i
        #pragma unroll
        for (int ot = 0; ot < 128; ot += 4) {
            int o = ot + o_sub;
            wt_s[i_sub][o] = W[o * DD + chunk * 32 + i_sub];
        }
        __syncthreads();
        #pragma unroll
        for (int kk = 0; kk < 32; kk++) {
            float w = wt_s[kk][tid];
            int kg = chunk * 32 + kk;
            #pragma unroll
            for (int r = 0; r < 32; r++)
                acc[r] = fmaf(x_s[r][kg], w, acc[r]);
        }
    }

    const float wq = w_q[tid], wk = w_k[tid], be = b_emb[tid];
    #pragma unroll 2
    for (int r = 0; r < 32; r++) {
        float v = acc[r] + be;
        g_seq[(row0 + r) * DD + tid] = v;
        float vq = v * wq;
        float vk = v * wk;
        #pragma unroll
        for (int off = 16; off > 0; off >>= 1) {
            vq += __shfl_xor_sync(0xffffffffu, vq, off);
            vk += __shfl_xor_sync(0xffffffffu, vk, off);
        }
        if (lane == 0) { red_q[warp][r] = vq; red_k[warp][r] = vk; }
    }
    __syncthreads();
    if (tid < 32) {
        g_q[row0 + tid] = red_q[0][tid] + red_q[1][tid] + red_q[2][tid] + red_q[3][tid] + b_q[0];
    } else if (tid < 64) {
        int r = tid - 32;
        g_k[row0 + r] = red_k[0][r] + red_k[1][r] + red_k[2][r] + red_k[3][r] + b_k[0];
    }
}

// ---------------------------------------------------------------------------
// Kernel 2: column softmax denominators.
// f values are bounded (|f| ~ 3) so no max-subtraction needed.
// g_rden[b,j] = 1 / sum_i exp(lrelu(adj[i,j]*(k[b,i]+q[b,j])))
// ---------------------------------------------------------------------------
__global__ __launch_bounds__(128) void k_denom(const float* __restrict__ adj)
{
    const int j = blockIdx.x * 128 + threadIdx.x;
    const int b = blockIdx.y;
    const float qv = g_q[b * NN + j];
    const float* __restrict__ kb = g_k + b * NN;

    float s = 0.f;
    #pragma unroll 8
    for (int i = 0; i < NN; i++) {
        float a = __ldg(adj + (size_t)i * NN + j);
        float f = a * (kb[i] + qv);
        f = (f > 0.f) ? f : 0.01f * f;
        s += __expf(f);
    }
    g_rden[b * NN + j] = 1.f / s;
}

// ---------------------------------------------------------------------------
// Kernel 3: vals[b,i,:] = sum_j P[b,i,j] * seq_fts[b,j,:]
// P generated on the fly into smem; mainloop uses packed fma.rn.f32x2.
// Block tile: 64 i x 128 d, J-tile = 32. 256 threads: warp->8 i rows,
// lane -> 4 d columns. acc = 8 x 2 f32x2 pairs per thread.
// ---------------------------------------------------------------------------
#define FMA2(d, a, b, c) asm("fma.rn.f32x2 %0, %1, %2, %3;" : "=l"(d) : "l"(a), "l"(b), "l"(c))
#define PACK2(d, lo, hi) asm("mov.b64 %0, {%1, %2};" : "=l"(d) : "f"(lo), "f"(hi))
#define UNPK2(lo, hi, s) asm("mov.b64 {%0, %1}, %2;" : "=f"(lo), "=f"(hi) : "l"(s))

__global__ __launch_bounds__(256) void k_attn(const float* __restrict__ adj,
                                              float* __restrict__ out)
{
    __shared__ __align__(16) float F_s[32][128];   // seq_fts tile [jj][d]
    __shared__ __align__(16) float P_s[64 * 36];   // P tile [ii][jj], pad 36

    const int tid  = threadIdx.x;
    const int warp = tid >> 5;
    const int lane = tid & 31;
    const int b  = blockIdx.y;
    const int i0 = blockIdx.x * 64;

    const float* __restrict__ seqb = g_seq + (size_t)b * NN * DD;
    const float* __restrict__ qb   = g_q + b * NN;
    const float* __restrict__ kb   = g_k + b * NN;
    const float* __restrict__ rb   = g_rden + b * NN;

    unsigned long long acc[8][2];
    #pragma unroll
    for (int i = 0; i < 8; i++) { acc[i][0] = 0ull; acc[i][1] = 0ull; }

    for (int j0 = 0; j0 < NN; j0 += 32) {
        __syncthreads();  // previous MMA done reading F_s/P_s

        // stage seq_fts tile (contiguous 32x128 block)
        {
            const float4* __restrict__ src = (const float4*)(seqb + (size_t)j0 * DD);
            float4* dst = (float4*)&F_s[0][0];
            #pragma unroll
            for (int t = 0; t < 4; t++) dst[t * 256 + tid] = src[t * 256 + tid];
        }

        // generate P tile: 2048 elements, 8 per thread, coalesced adj rows
        #pragma unroll
        for (int t = 0; t < 8; t++) {
            int lin = t * 256 + tid;
            int ii = lin >> 5;
            int jj = lin & 31;
            float a = adj[(size_t)(i0 + ii) * NN + j0 + jj];
            float f = a * (kb[i0 + ii] + qb[j0 + jj]);
            f = (f > 0.f) ? f : 0.01f * f;
            P_s[ii * 36 + jj] = __expf(f) * rb[j0 + jj];
        }
        __syncthreads();

        // MMA: acc[ii][d-pair] += P[ii][jj] * F[jj][d]
        const float4* P4 = (const float4*)P_s;  // row stride = 9 float4
        #pragma unroll
        for (int jg = 0; jg < 8; jg++) {
            unsigned long long fA[4][2];
            #pragma unroll
            for (int jj = 0; jj < 4; jj++) {
                float4 fv = *(const float4*)&F_s[jg * 4 + jj][lane * 4];
                PACK2(fA[jj][0], fv.x, fv.y);
                PACK2(fA[jj][1], fv.z, fv.w);
            }
            #pragma unroll
            for (int ii = 0; ii < 8; ii++) {
                float4 pv = P4[(warp * 8 + ii) * 9 + jg];  // broadcast
                unsigned long long pp;
                PACK2(pp, pv.x, pv.x);
                FMA2(acc[ii][0], pp, fA[0][0], acc[ii][0]);
                FMA2(acc[ii][1], pp, fA[0][1], acc[ii][1]);
                PACK2(pp, pv.y, pv.y);
                FMA2(acc[ii][0], pp, fA[1][0], acc[ii][0]);
                FMA2(acc[ii][1], pp, fA[1][1], acc[ii][1]);
                PACK2(pp, pv.z, pv.z);
                FMA2(acc[ii][0], pp, fA[2][0], acc[ii][0]);
                FMA2(acc[ii][1], pp, fA[2][1], acc[ii][1]);
                PACK2(pp, pv.w, pv.w);
                FMA2(acc[ii][0], pp, fA[3][0], acc[ii][0]);
                FMA2(acc[ii][1], pp, fA[3][1], acc[ii][1]);
            }
        }
    }

    // epilogue
    #pragma unroll
    for (int ii = 0; ii < 8; ii++) {
        int i = i0 + warp * 8 + ii;
        float4 v;
        UNPK2(v.x, v.y, acc[ii][0]);
        UNPK2(v.z, v.w, acc[ii][1]);
        *(float4*)&out[((size_t)b * NN + i) * DD + lane * 4] = v;
    }
}

// ---------------------------------------------------------------------------
extern "C" void kernel_launch(void* const* d_in, const int* in_sizes, int n_in,
                              void* d_out, int out_size)
{
    (void)in_sizes; (void)n_in; (void)out_size;
    const float* x     = (const float*)d_in[0];
    const float* adj   = (const float*)d_in[1];
    const float* W_emb = (const float*)d_in[2];
    const float* b_emb = (const float*)d_in[3];
    const float* w_q   = (const float*)d_in[4];
    const float* b_q   = (const float*)d_in[5];
    const float* w_k   = (const float*)d_in[6];
    const float* b_k   = (const float*)d_in[7];
    float* out = (float*)d_out;

    k_emb<<<(BB * NN) / 32, 128>>>(x, W_emb, b_emb, w_q, b_q, w_k, b_k);
    k_denom<<<dim3(NN / 128, BB), 128>>>(adj);
    k_attn<<<dim3(NN / 64, BB), 256>>>(adj, out);
}

// round 4
// speedup vs baseline: 2.0033x; 2.0033x over previous
#include <cuda_runtime.h>
#include <cuda_bf16.h>
#include <cstdint>

#define BB 16
#define NN 2048
#define DD 128

// scratch
__device__ float g_q[BB * NN];
__device__ float g_k[BB * NN];
__device__ float g_rden[BB * NN];
// seq_fts^T bf16 hi/lo, chunk-contiguous: [b][j/32][d][j%32]
__device__ __nv_bfloat16 g_hiT[(size_t)BB * DD * NN];
__device__ __nv_bfloat16 g_loT[(size_t)BB * DD * NN];

// ---------------------------------------------------------------------------
// helpers
// ---------------------------------------------------------------------------
__device__ __forceinline__ uint32_t smem_u32(const void* p) {
    uint32_t a;
    asm("{ .reg .u64 t; cvta.to.shared.u64 t, %1; cvt.u32.u64 %0, t; }" : "=r"(a) : "l"(p));
    return a;
}

// pitch: 40 bf16 = 80 bytes per 32-elem row (conflict-free for ldmatrix)
#define PITCHB 80
#define TILEB  (128 * PITCHB)   // 10240 bytes per operand buffer

__device__ __forceinline__ void ldmA4(uint32_t base, int lane, uint32_t* a) {
    uint32_t addr = base + (uint32_t)((lane & 15) * PITCHB) + (uint32_t)(((lane >> 4) & 1) << 4);
    asm volatile("ldmatrix.sync.aligned.m8n8.x4.shared.b16 {%0,%1,%2,%3}, [%4];"
                 : "=r"(a[0]), "=r"(a[1]), "=r"(a[2]), "=r"(a[3]) : "r"(addr));
}
// loads B frags for two adjacent n-tiles: r0,r1 = (b0,b1) of nt_even ; r2,r3 = nt_odd
__device__ __forceinline__ void ldmB4(uint32_t base, int lane, uint32_t* r) {
    uint32_t addr = base + (uint32_t)(((lane & 7) + ((lane >> 4) << 3)) * PITCHB)
                         + (uint32_t)(((lane >> 3) & 1) << 4);
    asm volatile("ldmatrix.sync.aligned.m8n8.x4.shared.b16 {%0,%1,%2,%3}, [%4];"
                 : "=r"(r[0]), "=r"(r[1]), "=r"(r[2]), "=r"(r[3]) : "r"(addr));
}
__device__ __forceinline__ void mma16816(float* d, const uint32_t* a, uint32_t b0, uint32_t b1) {
    asm volatile(
        "mma.sync.aligned.m16n8k16.row.col.f32.bf16.bf16.f32 "
        "{%0,%1,%2,%3}, {%4,%5,%6,%7}, {%8,%9}, {%0,%1,%2,%3};"
        : "+f"(d[0]), "+f"(d[1]), "+f"(d[2]), "+f"(d[3])
        : "r"(a[0]), "r"(a[1]), "r"(a[2]), "r"(a[3]), "r"(b0), "r"(b1));
}

// bf16 hi/lo split of a float -> packed bf16x2 words
__device__ __forceinline__ void split2(float v0, float v1, uint32_t& hw, uint32_t& lw) {
    __nv_bfloat16 h0 = __float2bfloat16(v0);
    __nv_bfloat16 h1 = __float2bfloat16(v1);
    __nv_bfloat162 hh; hh.x = h0; hh.y = h1;
    __nv_bfloat162 ll;
    ll.x = __float2bfloat16(v0 - __bfloat162float(h0));
    ll.y = __float2bfloat16(v1 - __bfloat162float(h1));
    hw = *(uint32_t*)&hh;
    lw = *(uint32_t*)&ll;
}

// shared mainloop over one 32-k chunk: NIT i-tiles of 16 rows per warp
template <int NIT>
__device__ __forceinline__ void mma_chunk(float (*acc)[4],
                                          uint32_t sAH, uint32_t sAL,
                                          uint32_t sBH, uint32_t sBL,
                                          int wr, int wc, int lane) {
    #pragma unroll
    for (int ks = 0; ks < 2; ks++) {
        uint32_t bh[8], bl[8];
        #pragma unroll
        for (int ntp = 0; ntp < 2; ntp++) {
            uint32_t boff = (uint32_t)((wc * 32 + ntp * 16) * PITCHB + ks * 32);
            ldmB4(sBH + boff, lane, bh + ntp * 4);
            ldmB4(sBL + boff, lane, bl + ntp * 4);
        }
        #pragma unroll
        for (int it = 0; it < NIT; it++) {
            uint32_t aoff = (uint32_t)(((wr * NIT + it) * 16) * PITCHB + ks * 32);
            uint32_t ah[4], al[4];
            ldmA4(sAH + aoff, lane, ah);
            ldmA4(sAL + aoff, lane, al);
            #pragma unroll
            for (int nt = 0; nt < 4; nt++) {
                mma16816(acc[it * 4 + nt], ah, bh[nt * 2], bh[nt * 2 + 1]);
                mma16816(acc[it * 4 + nt], ah, bl[nt * 2], bl[nt * 2 + 1]);
                mma16816(acc[it * 4 + nt], al, bh[nt * 2], bh[nt * 2 + 1]);
            }
        }
    }
}

// ---------------------------------------------------------------------------
// Kernel 1: seq_fts = x @ W^T + b_emb via mma.sync; emits q,k scalars and
// seq_fts^T hi/lo bf16 in chunk-contiguous layout.
// Block: 256 thr, tile 128 rows x 128 d, K chunked by 32.
// ---------------------------------------------------------------------------
__global__ __launch_bounds__(256) void k_emb(
    const float* __restrict__ x, const float* __restrict__ W,
    const float* __restrict__ b_emb,
    const float* __restrict__ w_q, const float* __restrict__ b_q,
    const float* __restrict__ w_k, const float* __restrict__ b_k)
{
    __shared__ __align__(16) uint8_t sm[4 * TILEB];      // AH AL BH BL
    __shared__ float qred[128], kred[128];

    const int tid  = threadIdx.x;
    const int lane = tid & 31;
    const int wid  = tid >> 5;
    const int wr   = wid >> 2;       // 0..1 : 64-row group
    const int wc   = wid & 3;        // 0..3 : 32-col group
    const int blk  = blockIdx.x;
    const size_t row0 = (size_t)blk * 128;

    if (tid < 128) { qred[tid] = 0.f; kred[tid] = 0.f; }

    const uint32_t sb  = smem_u32(sm);
    const uint32_t sAH = sb, sAL = sb + TILEB, sBH = sb + 2 * TILEB, sBL = sb + 3 * TILEB;

    float acc[16][4];
    #pragma unroll
    for (int i = 0; i < 16; i++)
        #pragma unroll
        for (int j = 0; j < 4; j++) acc[i][j] = 0.f;

    const int jj = (tid & 15) * 2;   // k-pair within chunk
    const int rb = tid >> 4;         // 0..15 row base

    for (int k0 = 0; k0 < DD; k0 += 32) {
        __syncthreads();
        #pragma unroll
        for (int g = 0; g < 8; g++) {
            int r = rb + g * 16;
            float2 xv = *(const float2*)(x + (row0 + r) * DD + k0 + jj);
            float2 wv = *(const float2*)(W + (size_t)r * DD + k0 + jj);
            uint32_t hw, lw;
            split2(xv.x, xv.y, hw, lw);
            *(uint32_t*)(sm + (size_t)0 * TILEB + r * PITCHB + jj * 2) = hw;
            *(uint32_t*)(sm + (size_t)1 * TILEB + r * PITCHB + jj * 2) = lw;
            split2(wv.x, wv.y, hw, lw);
            *(uint32_t*)(sm + (size_t)2 * TILEB + r * PITCHB + jj * 2) = hw;
            *(uint32_t*)(sm + (size_t)3 * TILEB + r * PITCHB + jj * 2) = lw;
        }
        __syncthreads();
        mma_chunk<4>(acc, sAH, sAL, sBH, sBL, wr, wc, lane);
    }

    // ---- epilogue: add bias, q/k partial reductions ----
    float2 be[4], wq2[4], wk2[4];
    #pragma unroll
    for (int nt = 0; nt < 4; nt++) {
        int c = wc * 32 + nt * 8 + (lane & 3) * 2;
        be[nt]  = *(const float2*)(b_emb + c);
        wq2[nt] = *(const float2*)(w_q + c);
        wk2[nt] = *(const float2*)(w_k + c);
    }
    __syncthreads();  // qred init visible

    #pragma unroll
    for (int it = 0; it < 4; it++) {
        float q0 = 0.f, q8 = 0.f, kk0 = 0.f, kk8 = 0.f;
        #pragma unroll
        for (int nt = 0; nt < 4; nt++) {
            float* a = acc[it * 4 + nt];
            a[0] += be[nt].x; a[1] += be[nt].y;
            a[2] += be[nt].x; a[3] += be[nt].y;
            q0 += a[0] * wq2[nt].x + a[1] * wq2[nt].y;
            q8 += a[2] * wq2[nt].x + a[3] * wq2[nt].y;
            kk0 += a[0] * wk2[nt].x + a[1] * wk2[nt].y;
            kk8 += a[2] * wk2[nt].x + a[3] * wk2[nt].y;
        }
        #pragma unroll
        for (int off = 1; off <= 2; off <<= 1) {
            q0 += __shfl_xor_sync(0xffffffffu, q0, off);
            q8 += __shfl_xor_sync(0xffffffffu, q8, off);
            kk0 += __shfl_xor_sync(0xffffffffu, kk0, off);
            kk8 += __shfl_xor_sync(0xffffffffu, kk8, off);
        }
        if ((lane & 3) == 0) {
            int r = wr * 64 + it * 16 + (lane >> 2);
            atomicAdd(&qred[r], q0);
            atomicAdd(&qred[r + 8], q8);
            atomicAdd(&kred[r], kk0);
            atomicAdd(&kred[r + 8], kk8);
        }
    }

    // ---- transpose + store hi then lo ----
    // T_s pitch 136 bf16 (272B) indexed [d][row]
    __nv_bfloat16* T = (__nv_bfloat16*)sm;
    const int b64 = (blk >> 4) * 64;          // b * 64 chunks
    const int jc0 = (blk & 15) * 4;           // first j-chunk of this tile

    #pragma unroll
    for (int pass = 0; pass < 2; pass++) {
        __syncthreads();
        #pragma unroll
        for (int it = 0; it < 4; it++) {
            int r = wr * 64 + it * 16 + (lane >> 2);
            #pragma unroll
            for (int nt = 0; nt < 4; nt++) {
                int c = wc * 32 + nt * 8 + (lane & 3) * 2;
                float* a = acc[it * 4 + nt];
                #pragma unroll
                for (int u = 0; u < 4; u++) {
                    float v = a[u];
                    __nv_bfloat16 h = __float2bfloat16(v);
                    __nv_bfloat16 o = pass == 0 ? h : __float2bfloat16(v - __bfloat162float(h));
                    T[(c + (u & 1)) * 136 + r + (u >> 1) * 8] = o;
                }
            }
        }
        __syncthreads();
        __nv_bfloat16* dstb = (pass == 0 ? g_hiT : g_loT);
        #pragma unroll
        for (int g = 0; g < 8; g++) {
            int lin = tid + g * 256;          // 0..2047
            int d   = lin >> 4;
            int seg = lin & 15;
            uint4 v = *(const uint4*)((const uint8_t*)T + d * 272 + seg * 16);
            size_t dst = (((size_t)(b64 + jc0 + (seg >> 2)) * 128 + d) * 32) + (seg & 3) * 8;
            *(uint4*)(dstb + dst) = v;
        }
    }

    __syncthreads();
    if (tid < 128) {
        g_q[row0 + tid] = qred[tid] + b_q[0];
        g_k[row0 + tid] = kred[tid] + b_k[0];
    }
}

// ---------------------------------------------------------------------------
// Kernel 2: column softmax denominators (softmax over i)
// ---------------------------------------------------------------------------
__global__ __launch_bounds__(128) void k_denom(const float* __restrict__ adj)
{
    const int j = blockIdx.x * 128 + threadIdx.x;
    const int b = blockIdx.y;
    const float qv = g_q[b * NN + j];
    const float* __restrict__ kb = g_k + b * NN;

    float s = 0.f;
    #pragma unroll 8
    for (int i = 0; i < NN; i++) {
        float a = __ldg(adj + (size_t)i * NN + j);
        float f = a * (kb[i] + qv);
        f = fmaxf(f, 0.01f * f);
        s += __expf(f);
    }
    g_rden[b * NN + j] = 1.f / s;
}

// ---------------------------------------------------------------------------
// Kernel 3: vals = softmax(f) @ seq_fts via mma.sync bf16-split.
// Block: 256 thr, tile 64 i x 128 d, j chunked by 32. grid (32, 16).
// ---------------------------------------------------------------------------
__global__ __launch_bounds__(256, 2) void k_attn(const float* __restrict__ adj,
                                                 float* __restrict__ out)
{
    __shared__ __align__(16) uint8_t sm[4 * TILEB];

    const int tid  = threadIdx.x;
    const int lane = tid & 31;
    const int wid  = tid >> 5;
    const int wr   = wid >> 2;        // 0..1 : 32-row group
    const int wc   = wid & 3;         // 0..3 : 32-col group
    const int b    = blockIdx.y;
    const int i0   = blockIdx.x * 64;

    const uint32_t sb  = smem_u32(sm);
    const uint32_t sAH = sb, sAL = sb + TILEB, sBH = sb + 2 * TILEB, sBL = sb + 3 * TILEB;

    const float* __restrict__ qb = g_q + b * NN;
    const float* __restrict__ kb = g_k + b * NN;
    const float* __restrict__ rb = g_rden + b * NN;
    const __nv_bfloat16* __restrict__ hi_b = g_hiT + (size_t)b * 64 * 128 * 32;
    const __nv_bfloat16* __restrict__ lo_b = g_loT + (size_t)b * 64 * 128 * 32;

    float acc[8][4];
    #pragma unroll
    for (int i = 0; i < 8; i++)
        #pragma unroll
        for (int j = 0; j < 4; j++) acc[i][j] = 0.f;

    const int jj = (tid & 15) * 2;    // j-pair within chunk
    const int ib = tid >> 4;          // 0..15 i base

    for (int j0 = 0; j0 < NN; j0 += 32) {
        __syncthreads();

        // stage B (seq_fts^T) hi/lo: contiguous 8KB each
        {
            const uint4* srch = (const uint4*)(hi_b + (size_t)(j0 >> 5) * 4096);
            const uint4* srcl = (const uint4*)(lo_b + (size_t)(j0 >> 5) * 4096);
            #pragma unroll
            for (int g = 0; g < 2; g++) {
                int idx = tid + g * 256;          // 0..511
                int d   = idx >> 2;
                int seg = idx & 3;
                *(uint4*)(sm + (size_t)2 * TILEB + d * PITCHB + seg * 16) = srch[idx];
                *(uint4*)(sm + (size_t)3 * TILEB + d * PITCHB + seg * 16) = srcl[idx];
            }
        }

        // generate A (P tile 64 x 32)
        {
            const float q0 = qb[j0 + jj], q1 = qb[j0 + jj + 1];
            const float r0 = rb[j0 + jj], r1 = rb[j0 + jj + 1];
            #pragma unroll
            for (int g = 0; g < 4; g++) {
                int i = ib + g * 16;
                float kv = kb[i0 + i];
                float2 a2 = *(const float2*)(adj + (size_t)(i0 + i) * NN + j0 + jj);
                float f0 = a2.x * (kv + q0); f0 = fmaxf(f0, 0.01f * f0);
                float f1 = a2.y * (kv + q1); f1 = fmaxf(f1, 0.01f * f1);
                float p0 = __expf(f0) * r0;
                float p1 = __expf(f1) * r1;
                uint32_t hw, lw;
                split2(p0, p1, hw, lw);
                *(uint32_t*)(sm + (size_t)0 * TILEB + i * PITCHB + jj * 2) = hw;
                *(uint32_t*)(sm + (size_t)1 * TILEB + i * PITCHB + jj * 2) = lw;
            }
        }
        __syncthreads();

        mma_chunk<2>(acc, sAH, sAL, sBH, sBL, wr, wc, lane);
    }

    // epilogue: direct float2 stores
    #pragma unroll
    for (int it = 0; it < 2; it++) {
        int r = i0 + wr * 32 + it * 16 + (lane >> 2);
        #pragma unroll
        for (int nt = 0; nt < 4; nt++) {
            int c = wc * 32 + nt * 8 + (lane & 3) * 2;
            float* a = acc[it * 4 + nt];
            *(float2*)(out + ((size_t)b * NN + r) * DD + c)     = make_float2(a[0], a[1]);
            *(float2*)(out + ((size_t)b * NN + r + 8) * DD + c) = make_float2(a[2], a[3]);
        }
    }
}

// ---------------------------------------------------------------------------
extern "C" void kernel_launch(void* const* d_in, const int* in_sizes, int n_in,
                              void* d_out, int out_size)
{
    (void)in_sizes; (void)n_in; (void)out_size;
    const float* x     = (const float*)d_in[0];
    const float* adj   = (const float*)d_in[1];
    const float* W_emb = (const float*)d_in[2];
    const float* b_emb = (const float*)d_in[3];
    const float* w_q   = (const float*)d_in[4];
    const float* b_q   = (const float*)d_in[5];
    const float* w_k   = (const float*)d_in[6];
    const float* b_k   = (const float*)d_in[7];
    float* out = (float*)d_out;

    k_emb<<<(BB * NN) / 128, 256>>>(x, W_emb, b_emb, w_q, b_q, w_k, b_k);
    k_denom<<<dim3(NN / 128, BB), 128>>>(adj);
    k_attn<<<dim3(NN / 64, BB), 256>>>(adj, out);
}

// round 5
// speedup vs baseline: 2.5242x; 1.2600x over previous
#include <cuda_runtime.h>
#include <cuda_bf16.h>
#include <cstdint>

#define BB 16
#define NN 2048
#define DD 128

// scratch
__device__ float g_q[BB * NN];
__device__ float g_k[BB * NN];
__device__ float g_rden[BB * NN];
__device__ float g_part[8][BB * NN];
// seq_fts^T bf16 hi/lo, chunk-contiguous: [b][j/32][d][j%32]
__device__ __nv_bfloat16 g_hiT[(size_t)BB * DD * NN];
__device__ __nv_bfloat16 g_loT[(size_t)BB * DD * NN];

// ---------------------------------------------------------------------------
// helpers
// ---------------------------------------------------------------------------
__device__ __forceinline__ uint32_t smem_u32(const void* p) {
    uint32_t a;
    asm("{ .reg .u64 t; cvta.to.shared.u64 t, %1; cvt.u32.u64 %0, t; }" : "=r"(a) : "l"(p));
    return a;
}

// pitch: 40 bf16 = 80 bytes per 32-elem row (conflict-free for ldmatrix)
#define PITCHB 80
#define TILEB  (128 * PITCHB)   // 10240 bytes (128-row operand)
#define ASZ    (64 * PITCHB)    // 5120 bytes (64-row A operand)
#define STAGE  (2 * ASZ + 2 * TILEB)  // AH AL BH BL = 30720

__device__ __forceinline__ void ldmA4(uint32_t base, int lane, uint32_t* a) {
    uint32_t addr = base + (uint32_t)((lane & 15) * PITCHB) + (uint32_t)(((lane >> 4) & 1) << 4);
    asm volatile("ldmatrix.sync.aligned.m8n8.x4.shared.b16 {%0,%1,%2,%3}, [%4];"
                 : "=r"(a[0]), "=r"(a[1]), "=r"(a[2]), "=r"(a[3]) : "r"(addr));
}
__device__ __forceinline__ void ldmB4(uint32_t base, int lane, uint32_t* r) {
    uint32_t addr = base + (uint32_t)(((lane & 7) + ((lane >> 4) << 3)) * PITCHB)
                         + (uint32_t)(((lane >> 3) & 1) << 4);
    asm volatile("ldmatrix.sync.aligned.m8n8.x4.shared.b16 {%0,%1,%2,%3}, [%4];"
                 : "=r"(r[0]), "=r"(r[1]), "=r"(r[2]), "=r"(r[3]) : "r"(addr));
}
__device__ __forceinline__ void mma16816(float* d, const uint32_t* a, uint32_t b0, uint32_t b1) {
    asm volatile(
        "mma.sync.aligned.m16n8k16.row.col.f32.bf16.bf16.f32 "
        "{%0,%1,%2,%3}, {%4,%5,%6,%7}, {%8,%9}, {%0,%1,%2,%3};"
        : "+f"(d[0]), "+f"(d[1]), "+f"(d[2]), "+f"(d[3])
        : "r"(a[0]), "r"(a[1]), "r"(a[2]), "r"(a[3]), "r"(b0), "r"(b1));
}

__device__ __forceinline__ void split2(float v0, float v1, uint32_t& hw, uint32_t& lw) {
    __nv_bfloat16 h0 = __float2bfloat16(v0);
    __nv_bfloat16 h1 = __float2bfloat16(v1);
    __nv_bfloat162 hh; hh.x = h0; hh.y = h1;
    __nv_bfloat162 ll;
    ll.x = __float2bfloat16(v0 - __bfloat162float(h0));
    ll.y = __float2bfloat16(v1 - __bfloat162float(h1));
    hw = *(uint32_t*)&hh;
    lw = *(uint32_t*)&ll;
}

template <int NIT>
__device__ __forceinline__ void mma_chunk(float (*acc)[4],
                                          uint32_t sAH, uint32_t sAL,
                                          uint32_t sBH, uint32_t sBL,
                                          int wr, int wc, int lane) {
    #pragma unroll
    for (int ks = 0; ks < 2; ks++) {
        uint32_t bh[8], bl[8];
        #pragma unroll
        for (int ntp = 0; ntp < 2; ntp++) {
            uint32_t boff = (uint32_t)((wc * 32 + ntp * 16) * PITCHB + ks * 32);
            ldmB4(sBH + boff, lane, bh + ntp * 4);
            ldmB4(sBL + boff, lane, bl + ntp * 4);
        }
        #pragma unroll
        for (int it = 0; it < NIT; it++) {
            uint32_t aoff = (uint32_t)(((wr * NIT + it) * 16) * PITCHB + ks * 32);
            uint32_t ah[4], al[4];
            ldmA4(sAH + aoff, lane, ah);
            ldmA4(sAL + aoff, lane, al);
            #pragma unroll
            for (int nt = 0; nt < 4; nt++) {
                mma16816(acc[it * 4 + nt], ah, bh[nt * 2], bh[nt * 2 + 1]);
                mma16816(acc[it * 4 + nt], ah, bl[nt * 2], bl[nt * 2 + 1]);
                mma16816(acc[it * 4 + nt], al, bh[nt * 2], bh[nt * 2 + 1]);
            }
        }
    }
}

// ---------------------------------------------------------------------------
// Kernel 1: seq_fts GEMM (unchanged from passing R4 version)
// ---------------------------------------------------------------------------
__global__ __launch_bounds__(256) void k_emb(
    const float* __restrict__ x, const float* __restrict__ W,
    const float* __restrict__ b_emb,
    const float* __restrict__ w_q, const float* __restrict__ b_q,
    const float* __restrict__ w_k, const float* __restrict__ b_k)
{
    __shared__ __align__(16) uint8_t sm[4 * TILEB];
    __shared__ float qred[128], kred[128];

    const int tid  = threadIdx.x;
    const int lane = tid & 31;
    const int wid  = tid >> 5;
    const int wr   = wid >> 2;
    const int wc   = wid & 3;
    const int blk  = blockIdx.x;
    const size_t row0 = (size_t)blk * 128;

    if (tid < 128) { qred[tid] = 0.f; kred[tid] = 0.f; }

    const uint32_t sb  = smem_u32(sm);
    const uint32_t sAH = sb, sAL = sb + TILEB, sBH = sb + 2 * TILEB, sBL = sb + 3 * TILEB;

    float acc[16][4];
    #pragma unroll
    for (int i = 0; i < 16; i++)
        #pragma unroll
        for (int j = 0; j < 4; j++) acc[i][j] = 0.f;

    const int jj = (tid & 15) * 2;
    const int rb = tid >> 4;

    for (int k0 = 0; k0 < DD; k0 += 32) {
        __syncthreads();
        #pragma unroll
        for (int g = 0; g < 8; g++) {
            int r = rb + g * 16;
            float2 xv = *(const float2*)(x + (row0 + r) * DD + k0 + jj);
            float2 wv = *(const float2*)(W + (size_t)r * DD + k0 + jj);
            uint32_t hw, lw;
            split2(xv.x, xv.y, hw, lw);
            *(uint32_t*)(sm + (size_t)0 * TILEB + r * PITCHB + jj * 2) = hw;
            *(uint32_t*)(sm + (size_t)1 * TILEB + r * PITCHB + jj * 2) = lw;
            split2(wv.x, wv.y, hw, lw);
            *(uint32_t*)(sm + (size_t)2 * TILEB + r * PITCHB + jj * 2) = hw;
            *(uint32_t*)(sm + (size_t)3 * TILEB + r * PITCHB + jj * 2) = lw;
        }
        __syncthreads();
        mma_chunk<4>(acc, sAH, sAL, sBH, sBL, wr, wc, lane);
    }

    float2 be[4], wq2[4], wk2[4];
    #pragma unroll
    for (int nt = 0; nt < 4; nt++) {
        int c = wc * 32 + nt * 8 + (lane & 3) * 2;
        be[nt]  = *(const float2*)(b_emb + c);
        wq2[nt] = *(const float2*)(w_q + c);
        wk2[nt] = *(const float2*)(w_k + c);
    }
    __syncthreads();

    #pragma unroll
    for (int it = 0; it < 4; it++) {
        float q0 = 0.f, q8 = 0.f, kk0 = 0.f, kk8 = 0.f;
        #pragma unroll
        for (int nt = 0; nt < 4; nt++) {
            float* a = acc[it * 4 + nt];
            a[0] += be[nt].x; a[1] += be[nt].y;
            a[2] += be[nt].x; a[3] += be[nt].y;
            q0 += a[0] * wq2[nt].x + a[1] * wq2[nt].y;
            q8 += a[2] * wq2[nt].x + a[3] * wq2[nt].y;
            kk0 += a[0] * wk2[nt].x + a[1] * wk2[nt].y;
            kk8 += a[2] * wk2[nt].x + a[3] * wk2[nt].y;
        }
        #pragma unroll
        for (int off = 1; off <= 2; off <<= 1) {
            q0 += __shfl_xor_sync(0xffffffffu, q0, off);
            q8 += __shfl_xor_sync(0xffffffffu, q8, off);
            kk0 += __shfl_xor_sync(0xffffffffu, kk0, off);
            kk8 += __shfl_xor_sync(0xffffffffu, kk8, off);
        }
        if ((lane & 3) == 0) {
            int r = wr * 64 + it * 16 + (lane >> 2);
            atomicAdd(&qred[r], q0);
            atomicAdd(&qred[r + 8], q8);
            atomicAdd(&kred[r], kk0);
            atomicAdd(&kred[r + 8], kk8);
        }
    }

    __nv_bfloat16* T = (__nv_bfloat16*)sm;
    const int b64 = (blk >> 4) * 64;
    const int jc0 = (blk & 15) * 4;

    #pragma unroll
    for (int pass = 0; pass < 2; pass++) {
        __syncthreads();
        #pragma unroll
        for (int it = 0; it < 4; it++) {
            int r = wr * 64 + it * 16 + (lane >> 2);
            #pragma unroll
            for (int nt = 0; nt < 4; nt++) {
                int c = wc * 32 + nt * 8 + (lane & 3) * 2;
                float* a = acc[it * 4 + nt];
                #pragma unroll
                for (int u = 0; u < 4; u++) {
                    float v = a[u];
                    __nv_bfloat16 h = __float2bfloat16(v);
                    __nv_bfloat16 o = pass == 0 ? h : __float2bfloat16(v - __bfloat162float(h));
                    T[(c + (u & 1)) * 136 + r + (u >> 1) * 8] = o;
                }
            }
        }
        __syncthreads();
        __nv_bfloat16* dstb = (pass == 0 ? g_hiT : g_loT);
        #pragma unroll
        for (int g = 0; g < 8; g++) {
            int lin = tid + g * 256;
            int d   = lin >> 4;
            int seg = lin & 15;
            uint4 v = *(const uint4*)((const uint8_t*)T + d * 272 + seg * 16);
            size_t dst = (((size_t)(b64 + jc0 + (seg >> 2)) * 128 + d) * 32) + (seg & 3) * 8;
            *(uint4*)(dstb + dst) = v;
        }
    }

    __syncthreads();
    if (tid < 128) {
        g_q[row0 + tid] = qred[tid] + b_q[0];
        g_k[row0 + tid] = kred[tid] + b_k[0];
    }
}

// ---------------------------------------------------------------------------
// Kernel 2a: partial column sums (8-way i-split, no atomics)
// ---------------------------------------------------------------------------
__global__ __launch_bounds__(128) void k_denom(const float* __restrict__ adj)
{
    const int j  = blockIdx.x * 128 + threadIdx.x;
    const int b  = blockIdx.y;
    const int i0 = blockIdx.z * 256;
    const float qv = g_q[b * NN + j];
    const float* __restrict__ kb = g_k + b * NN;

    float s = 0.f;
    #pragma unroll 8
    for (int i = i0; i < i0 + 256; i++) {
        float a = __ldg(adj + (size_t)i * NN + j);
        float f = a * (kb[i] + qv);
        f = fmaxf(f, 0.01f * f);
        s += __expf(f);
    }
    g_part[blockIdx.z][b * NN + j] = s;
}

// Kernel 2b: reduce partials -> reciprocal denominators
__global__ __launch_bounds__(256) void k_rcp()
{
    const int idx = blockIdx.x * 256 + threadIdx.x;
    float s = 0.f;
    #pragma unroll
    for (int p = 0; p < 8; p++) s += g_part[p][idx];
    g_rden[idx] = __frcp_rn(s);
}

// ---------------------------------------------------------------------------
// Kernel 3: pipelined attention GEMM. Tile 64i x 128d, j-chunk 32,
// double-buffered smem stages, loads-then-MMA-then-convert per iteration.
// ---------------------------------------------------------------------------
__global__ __launch_bounds__(256, 2) void k_attn(const float* __restrict__ adj,
                                                 float* __restrict__ out)
{
    extern __shared__ __align__(16) uint8_t smd[];   // 2 * STAGE

    const int tid  = threadIdx.x;
    const int lane = tid & 31;
    const int wid  = tid >> 5;
    const int wr   = wid >> 2;        // 0..1 : 32-row group
    const int wc   = wid & 3;         // 0..3 : 32-col group
    const int b    = blockIdx.y;
    const int i0   = blockIdx.x * 64;

    const uint32_t sb = smem_u32(smd);

    const float* __restrict__ qb = g_q + b * NN;
    const float* __restrict__ kb = g_k + b * NN;
    const float* __restrict__ rb = g_rden + b * NN;
    const __nv_bfloat16* __restrict__ hi_b = g_hiT + (size_t)b * DD * NN;
    const __nv_bfloat16* __restrict__ lo_b = g_loT + (size_t)b * DD * NN;

    float acc[8][4];
    #pragma unroll
    for (int i = 0; i < 8; i++)
        #pragma unroll
        for (int j = 0; j < 4; j++) acc[i][j] = 0.f;

    const int jj = (tid & 15) * 2;    // j-pair within chunk
    const int ib = tid >> 4;          // 0..15 i base

    // k values are chunk-invariant
    float kv[4];
    #pragma unroll
    for (int g = 0; g < 4; g++) kv[g] = kb[i0 + ib + g * 16];

    // ---- prologue: stage chunk 0 into stage 0 ----
    {
        const float q0 = qb[jj], q1 = qb[jj + 1];
        const float r0 = rb[jj], r1 = rb[jj + 1];
        #pragma unroll
        for (int g = 0; g < 4; g++) {
            int i = ib + g * 16;
            float2 a2 = *(const float2*)(adj + (size_t)(i0 + i) * NN + jj);
            float f0 = a2.x * (kv[g] + q0); f0 = fmaxf(f0, 0.01f * f0);
            float f1 = a2.y * (kv[g] + q1); f1 = fmaxf(f1, 0.01f * f1);
            uint32_t hw, lw;
            split2(__expf(f0) * r0, __expf(f1) * r1, hw, lw);
            *(uint32_t*)(smd + i * PITCHB + jj * 2) = hw;
            *(uint32_t*)(smd + ASZ + i * PITCHB + jj * 2) = lw;
        }
        const uint4* srch = (const uint4*)hi_b;
        const uint4* srcl = (const uint4*)lo_b;
        #pragma unroll
        for (int g = 0; g < 2; g++) {
            int idx = tid + g * 256;
            int d = idx >> 2, seg = idx & 3;
            *(uint4*)(smd + 2 * ASZ + d * PITCHB + seg * 16) = srch[idx];
            *(uint4*)(smd + 2 * ASZ + TILEB + d * PITCHB + seg * 16) = srcl[idx];
        }
    }
    __syncthreads();

    for (int c = 0; c < 64; c++) {
        const uint32_t cur = sb + (uint32_t)((c & 1) * STAGE);
        uint8_t* nxt = smd + ((c + 1) & 1) * STAGE;
        const bool pf = (c < 63);
        const int j0n = (c + 1) * 32;

        // (a) issue next chunk's global loads
        float2 adjv[4];
        uint4 bh2[2], bl2[2];
        float q0 = 0.f, q1 = 0.f, r0 = 0.f, r1 = 0.f;
        if (pf) {
            q0 = qb[j0n + jj]; q1 = qb[j0n + jj + 1];
            r0 = rb[j0n + jj]; r1 = rb[j0n + jj + 1];
            #pragma unroll
            for (int g = 0; g < 4; g++)
                adjv[g] = *(const float2*)(adj + (size_t)(i0 + ib + g * 16) * NN + j0n + jj);
            const uint4* srch = (const uint4*)(hi_b + (size_t)(j0n >> 5) * 4096);
            const uint4* srcl = (const uint4*)(lo_b + (size_t)(j0n >> 5) * 4096);
            bh2[0] = srch[tid]; bh2[1] = srch[tid + 256];
            bl2[0] = srcl[tid]; bl2[1] = srcl[tid + 256];
        }

        // (b) MMA on current stage
        mma_chunk<2>(acc, cur, cur + ASZ, cur + 2 * ASZ, cur + 2 * ASZ + TILEB, wr, wc, lane);

        // (c) convert + store next stage
        if (pf) {
            #pragma unroll
            for (int g = 0; g < 4; g++) {
                int i = ib + g * 16;
                float f0 = adjv[g].x * (kv[g] + q0); f0 = fmaxf(f0, 0.01f * f0);
                float f1 = adjv[g].y * (kv[g] + q1); f1 = fmaxf(f1, 0.01f * f1);
                uint32_t hw, lw;
                split2(__expf(f0) * r0, __expf(f1) * r1, hw, lw);
                *(uint32_t*)(nxt + i * PITCHB + jj * 2) = hw;
                *(uint32_t*)(nxt + ASZ + i * PITCHB + jj * 2) = lw;
            }
            #pragma unroll
            for (int g = 0; g < 2; g++) {
                int idx = tid + g * 256;
                int d = idx >> 2, seg = idx & 3;
                *(uint4*)(nxt + 2 * ASZ + d * PITCHB + seg * 16) = bh2[g];
                *(uint4*)(nxt + 2 * ASZ + TILEB + d * PITCHB + seg * 16) = bl2[g];
            }
        }
        __syncthreads();
    }

    // epilogue
    #pragma unroll
    for (int it = 0; it < 2; it++) {
        int r = i0 + wr * 32 + it * 16 + (lane >> 2);
        #pragma unroll
        for (int nt = 0; nt < 4; nt++) {
            int c = wc * 32 + nt * 8 + (lane & 3) * 2;
            float* a = acc[it * 4 + nt];
            *(float2*)(out + ((size_t)b * NN + r) * DD + c)     = make_float2(a[0], a[1]);
            *(float2*)(out + ((size_t)b * NN + r + 8) * DD + c) = make_float2(a[2], a[3]);
        }
    }
}

// ---------------------------------------------------------------------------
extern "C" void kernel_launch(void* const* d_in, const int* in_sizes, int n_in,
                              void* d_out, int out_size)
{
    (void)in_sizes; (void)n_in; (void)out_size;
    const float* x     = (const float*)d_in[0];
    const float* adj   = (const float*)d_in[1];
    const float* W_emb = (const float*)d_in[2];
    const float* b_emb = (const float*)d_in[3];
    const float* w_q   = (const float*)d_in[4];
    const float* b_q   = (const float*)d_in[5];
    const float* w_k   = (const float*)d_in[6];
    const float* b_k   = (const float*)d_in[7];
    float* out = (float*)d_out;

    static bool attr_set = false;
    if (!attr_set) {
        cudaFuncSetAttribute(k_attn, cudaFuncAttributeMaxDynamicSharedMemorySize, 2 * STAGE);
        attr_set = true;
    }

    k_emb<<<(BB * NN) / 128, 256>>>(x, W_emb, b_emb, w_q, b_q, w_k, b_k);
    k_denom<<<dim3(NN / 128, BB, 8), 128>>>(adj);
    k_rcp<<<BB * NN / 256, 256>>>();
    k_attn<<<dim3(NN / 64, BB), 256, 2 * STAGE>>>(adj, out);
}

// round 6
// speedup vs baseline: 3.0406x; 1.2046x over previous
#include <cuda_runtime.h>
#include <cuda_fp16.h>
#include <cstdint>

#define BB 16
#define NN 2048
#define DD 128

// scratch
__device__ float g_q[BB * NN];
__device__ float g_k[BB * NN];
__device__ float g_rden[BB * NN];
__device__ float g_part[8][BB * NN];
// seq_fts^T fp16 hi/lo, chunk-contiguous: [b][j/32][d][j%32]
__device__ __half g_hiT[(size_t)BB * DD * NN];
__device__ __half g_loT[(size_t)BB * DD * NN];

// ---------------------------------------------------------------------------
// helpers
// ---------------------------------------------------------------------------
__device__ __forceinline__ uint32_t smem_u32(const void* p) {
    uint32_t a;
    asm("{ .reg .u64 t; cvta.to.shared.u64 t, %1; cvt.u32.u64 %0, t; }" : "=r"(a) : "l"(p));
    return a;
}

// pitch: 40 f16 = 80 bytes per 32-elem row (conflict-free for ldmatrix)
#define PITCHB 80
#define TILEB  (128 * PITCHB)   // 10240 bytes (128-row operand)
#define ASZ    (64 * PITCHB)    // 5120 bytes (64-row A operand)
#define STAGE  (ASZ + 2 * TILEB)  // A BH BL = 25600

__device__ __forceinline__ void ldmA4(uint32_t base, int lane, uint32_t* a) {
    uint32_t addr = base + (uint32_t)((lane & 15) * PITCHB) + (uint32_t)(((lane >> 4) & 1) << 4);
    asm volatile("ldmatrix.sync.aligned.m8n8.x4.shared.b16 {%0,%1,%2,%3}, [%4];"
                 : "=r"(a[0]), "=r"(a[1]), "=r"(a[2]), "=r"(a[3]) : "r"(addr));
}
__device__ __forceinline__ void ldmB4(uint32_t base, int lane, uint32_t* r) {
    uint32_t addr = base + (uint32_t)(((lane & 7) + ((lane >> 4) << 3)) * PITCHB)
                         + (uint32_t)(((lane >> 3) & 1) << 4);
    asm volatile("ldmatrix.sync.aligned.m8n8.x4.shared.b16 {%0,%1,%2,%3}, [%4];"
                 : "=r"(r[0]), "=r"(r[1]), "=r"(r[2]), "=r"(r[3]) : "r"(addr));
}
__device__ __forceinline__ void mma16816h(float* d, const uint32_t* a, uint32_t b0, uint32_t b1) {
    asm volatile(
        "mma.sync.aligned.m16n8k16.row.col.f32.f16.f16.f32 "
        "{%0,%1,%2,%3}, {%4,%5,%6,%7}, {%8,%9}, {%0,%1,%2,%3};"
        : "+f"(d[0]), "+f"(d[1]), "+f"(d[2]), "+f"(d[3])
        : "r"(a[0]), "r"(a[1]), "r"(a[2]), "r"(a[3]), "r"(b0), "r"(b1));
}

// fp16 hi/lo split of two floats -> packed half2 words
__device__ __forceinline__ void split2h(float v0, float v1, uint32_t& hw, uint32_t& lw) {
    __half h0 = __float2half_rn(v0);
    __half h1 = __float2half_rn(v1);
    __half2 hh; hh.x = h0; hh.y = h1;
    __half2 ll;
    ll.x = __float2half_rn(v0 - __half2float(h0));
    ll.y = __float2half_rn(v1 - __half2float(h1));
    hw = *(uint32_t*)&hh;
    lw = *(uint32_t*)&ll;
}
__device__ __forceinline__ uint32_t pack2h(float v0, float v1) {
    __half2 hh; hh.x = __float2half_rn(v0); hh.y = __float2half_rn(v1);
    return *(uint32_t*)&hh;
}

// 3-term split mainloop (k_emb): A hi/lo x B hi/lo, drop lo*lo
template <int NIT>
__device__ __forceinline__ void mma_chunk3(float (*acc)[4],
                                           uint32_t sAH, uint32_t sAL,
                                           uint32_t sBH, uint32_t sBL,
                                           int wr, int wc, int lane) {
    #pragma unroll
    for (int ks = 0; ks < 2; ks++) {
        uint32_t bh[8], bl[8];
        #pragma unroll
        for (int ntp = 0; ntp < 2; ntp++) {
            uint32_t boff = (uint32_t)((wc * 32 + ntp * 16) * PITCHB + ks * 32);
            ldmB4(sBH + boff, lane, bh + ntp * 4);
            ldmB4(sBL + boff, lane, bl + ntp * 4);
        }
        #pragma unroll
        for (int it = 0; it < NIT; it++) {
            uint32_t aoff = (uint32_t)(((wr * NIT + it) * 16) * PITCHB + ks * 32);
            uint32_t ah[4], al[4];
            ldmA4(sAH + aoff, lane, ah);
            ldmA4(sAL + aoff, lane, al);
            #pragma unroll
            for (int nt = 0; nt < 4; nt++) {
                mma16816h(acc[it * 4 + nt], ah, bh[nt * 2], bh[nt * 2 + 1]);
                mma16816h(acc[it * 4 + nt], ah, bl[nt * 2], bl[nt * 2 + 1]);
                mma16816h(acc[it * 4 + nt], al, bh[nt * 2], bh[nt * 2 + 1]);
            }
        }
    }
}

// 2-term mainloop (k_attn): A single fp16 x B hi/lo
template <int NIT>
__device__ __forceinline__ void mma_chunk2(float (*acc)[4],
                                           uint32_t sA,
                                           uint32_t sBH, uint32_t sBL,
                                           int wr, int wc, int lane) {
    #pragma unroll
    for (int ks = 0; ks < 2; ks++) {
        uint32_t bh[8], bl[8];
        #pragma unroll
        for (int ntp = 0; ntp < 2; ntp++) {
            uint32_t boff = (uint32_t)((wc * 32 + ntp * 16) * PITCHB + ks * 32);
            ldmB4(sBH + boff, lane, bh + ntp * 4);
            ldmB4(sBL + boff, lane, bl + ntp * 4);
        }
        #pragma unroll
        for (int it = 0; it < NIT; it++) {
            uint32_t aoff = (uint32_t)(((wr * NIT + it) * 16) * PITCHB + ks * 32);
            uint32_t ah[4];
            ldmA4(sA + aoff, lane, ah);
            #pragma unroll
            for (int nt = 0; nt < 4; nt++) {
                mma16816h(acc[it * 4 + nt], ah, bh[nt * 2], bh[nt * 2 + 1]);
                mma16816h(acc[it * 4 + nt], ah, bl[nt * 2], bl[nt * 2 + 1]);
            }
        }
    }
}

// ---------------------------------------------------------------------------
// Kernel 1: seq_fts = x @ W^T + b_emb via fp16-split mma.sync.
// ---------------------------------------------------------------------------
__global__ __launch_bounds__(256) void k_emb(
    const float* __restrict__ x, const float* __restrict__ W,
    const float* __restrict__ b_emb,
    const float* __restrict__ w_q, const float* __restrict__ b_q,
    const float* __restrict__ w_k, const float* __restrict__ b_k)
{
    __shared__ __align__(16) uint8_t sm[4 * TILEB];
    __shared__ float qred[128], kred[128];

    const int tid  = threadIdx.x;
    const int lane = tid & 31;
    const int wid  = tid >> 5;
    const int wr   = wid >> 2;
    const int wc   = wid & 3;
    const int blk  = blockIdx.x;
    const size_t row0 = (size_t)blk * 128;

    if (tid < 128) { qred[tid] = 0.f; kred[tid] = 0.f; }

    const uint32_t sb  = smem_u32(sm);
    const uint32_t sAH = sb, sAL = sb + TILEB, sBH = sb + 2 * TILEB, sBL = sb + 3 * TILEB;

    float acc[16][4];
    #pragma unroll
    for (int i = 0; i < 16; i++)
        #pragma unroll
        for (int j = 0; j < 4; j++) acc[i][j] = 0.f;

    const int jj = (tid & 15) * 2;
    const int rb = tid >> 4;

    for (int k0 = 0; k0 < DD; k0 += 32) {
        __syncthreads();
        #pragma unroll
        for (int g = 0; g < 8; g++) {
            int r = rb + g * 16;
            float2 xv = *(const float2*)(x + (row0 + r) * DD + k0 + jj);
            float2 wv = *(const float2*)(W + (size_t)r * DD + k0 + jj);
            uint32_t hw, lw;
            split2h(xv.x, xv.y, hw, lw);
            *(uint32_t*)(sm + (size_t)0 * TILEB + r * PITCHB + jj * 2) = hw;
            *(uint32_t*)(sm + (size_t)1 * TILEB + r * PITCHB + jj * 2) = lw;
            split2h(wv.x, wv.y, hw, lw);
            *(uint32_t*)(sm + (size_t)2 * TILEB + r * PITCHB + jj * 2) = hw;
            *(uint32_t*)(sm + (size_t)3 * TILEB + r * PITCHB + jj * 2) = lw;
        }
        __syncthreads();
        mma_chunk3<4>(acc, sAH, sAL, sBH, sBL, wr, wc, lane);
    }

    float2 be[4], wq2[4], wk2[4];
    #pragma unroll
    for (int nt = 0; nt < 4; nt++) {
        int c = wc * 32 + nt * 8 + (lane & 3) * 2;
        be[nt]  = *(const float2*)(b_emb + c);
        wq2[nt] = *(const float2*)(w_q + c);
        wk2[nt] = *(const float2*)(w_k + c);
    }
    __syncthreads();

    #pragma unroll
    for (int it = 0; it < 4; it++) {
        float q0 = 0.f, q8 = 0.f, kk0 = 0.f, kk8 = 0.f;
        #pragma unroll
        for (int nt = 0; nt < 4; nt++) {
            float* a = acc[it * 4 + nt];
            a[0] += be[nt].x; a[1] += be[nt].y;
            a[2] += be[nt].x; a[3] += be[nt].y;
            q0 += a[0] * wq2[nt].x + a[1] * wq2[nt].y;
            q8 += a[2] * wq2[nt].x + a[3] * wq2[nt].y;
            kk0 += a[0] * wk2[nt].x + a[1] * wk2[nt].y;
            kk8 += a[2] * wk2[nt].x + a[3] * wk2[nt].y;
        }
        #pragma unroll
        for (int off = 1; off <= 2; off <<= 1) {
            q0 += __shfl_xor_sync(0xffffffffu, q0, off);
            q8 += __shfl_xor_sync(0xffffffffu, q8, off);
            kk0 += __shfl_xor_sync(0xffffffffu, kk0, off);
            kk8 += __shfl_xor_sync(0xffffffffu, kk8, off);
        }
        if ((lane & 3) == 0) {
            int r = wr * 64 + it * 16 + (lane >> 2);
            atomicAdd(&qred[r], q0);
            atomicAdd(&qred[r + 8], q8);
            atomicAdd(&kred[r], kk0);
            atomicAdd(&kred[r + 8], kk8);
        }
    }

    // ---- transpose + store hi then lo (fp16) ----
    __half* T = (__half*)sm;
    const int b64 = (blk >> 4) * 64;
    const int jc0 = (blk & 15) * 4;

    #pragma unroll
    for (int pass = 0; pass < 2; pass++) {
        __syncthreads();
        #pragma unroll
        for (int it = 0; it < 4; it++) {
            int r = wr * 64 + it * 16 + (lane >> 2);
            #pragma unroll
            for (int nt = 0; nt < 4; nt++) {
                int c = wc * 32 + nt * 8 + (lane & 3) * 2;
                float* a = acc[it * 4 + nt];
                #pragma unroll
                for (int u = 0; u < 4; u++) {
                    float v = a[u];
                    __half h = __float2half_rn(v);
                    __half o = pass == 0 ? h : __float2half_rn(v - __half2float(h));
                    T[(c + (u & 1)) * 136 + r + (u >> 1) * 8] = o;
                }
            }
        }
        __syncthreads();
        __half* dstb = (pass == 0 ? g_hiT : g_loT);
        #pragma unroll
        for (int g = 0; g < 8; g++) {
            int lin = tid + g * 256;
            int d   = lin >> 4;
            int seg = lin & 15;
            uint4 v = *(const uint4*)((const uint8_t*)T + d * 272 + seg * 16);
            size_t dst = (((size_t)(b64 + jc0 + (seg >> 2)) * 128 + d) * 32) + (seg & 3) * 8;
            *(uint4*)(dstb + dst) = v;
        }
    }

    __syncthreads();
    if (tid < 128) {
        g_q[row0 + tid] = qred[tid] + b_q[0];
        g_k[row0 + tid] = kred[tid] + b_k[0];
    }
}

// ---------------------------------------------------------------------------
// Kernel 2a: partial column sums (8-way i-split)
// ---------------------------------------------------------------------------
__global__ __launch_bounds__(128) void k_denom(const float* __restrict__ adj)
{
    const int j  = blockIdx.x * 128 + threadIdx.x;
    const int b  = blockIdx.y;
    const int i0 = blockIdx.z * 256;
    const float qv = g_q[b * NN + j];
    const float* __restrict__ kb = g_k + b * NN;

    float s = 0.f;
    #pragma unroll 8
    for (int i = i0; i < i0 + 256; i++) {
        float a = __ldg(adj + (size_t)i * NN + j);
        float f = a * (kb[i] + qv);
        f = fmaxf(f, 0.01f * f);
        s += __expf(f);
    }
    g_part[blockIdx.z][b * NN + j] = s;
}

__global__ __launch_bounds__(256) void k_rcp()
{
    const int idx = blockIdx.x * 256 + threadIdx.x;
    float s = 0.f;
    #pragma unroll
    for (int p = 0; p < 8; p++) s += g_part[p][idx];
    g_rden[idx] = __frcp_rn(s);
}

// ---------------------------------------------------------------------------
// Kernel 3: pipelined attention GEMM, A single fp16 / B fp16 hi-lo (2 MMAs).
// ---------------------------------------------------------------------------
__global__ __launch_bounds__(256, 2) void k_attn(const float* __restrict__ adj,
                                                 float* __restrict__ out)
{
    extern __shared__ __align__(16) uint8_t smd[];   // 2 * STAGE

    const int tid  = threadIdx.x;
    const int lane = tid & 31;
    const int wid  = tid >> 5;
    const int wr   = wid >> 2;
    const int wc   = wid & 3;
    const int b    = blockIdx.y;
    const int i0   = blockIdx.x * 64;

    const uint32_t sb = smem_u32(smd);

    const float* __restrict__ qb = g_q + b * NN;
    const float* __restrict__ kb = g_k + b * NN;
    const float* __restrict__ rb = g_rden + b * NN;
    const __half* __restrict__ hi_b = g_hiT + (size_t)b * DD * NN;
    const __half* __restrict__ lo_b = g_loT + (size_t)b * DD * NN;

    float acc[8][4];
    #pragma unroll
    for (int i = 0; i < 8; i++)
        #pragma unroll
        for (int j = 0; j < 4; j++) acc[i][j] = 0.f;

    const int jj = (tid & 15) * 2;
    const int ib = tid >> 4;

    float kv[4];
    #pragma unroll
    for (int g = 0; g < 4; g++) kv[g] = kb[i0 + ib + g * 16];

    // ---- prologue: stage chunk 0 ----
    {
        const float q0 = qb[jj], q1 = qb[jj + 1];
        const float r0 = rb[jj], r1 = rb[jj + 1];
        #pragma unroll
        for (int g = 0; g < 4; g++) {
            int i = ib + g * 16;
            float2 a2 = *(const float2*)(adj + (size_t)(i0 + i) * NN + jj);
            float f0 = a2.x * (kv[g] + q0); f0 = fmaxf(f0, 0.01f * f0);
            float f1 = a2.y * (kv[g] + q1); f1 = fmaxf(f1, 0.01f * f1);
            *(uint32_t*)(smd + i * PITCHB + jj * 2) = pack2h(__expf(f0) * r0, __expf(f1) * r1);
        }
        const uint4* srch = (const uint4*)hi_b;
        const uint4* srcl = (const uint4*)lo_b;
        #pragma unroll
        for (int g = 0; g < 2; g++) {
            int idx = tid + g * 256;
            int d = idx >> 2, seg = idx & 3;
            *(uint4*)(smd + ASZ + d * PITCHB + seg * 16) = srch[idx];
            *(uint4*)(smd + ASZ + TILEB + d * PITCHB + seg * 16) = srcl[idx];
        }
    }
    __syncthreads();

    for (int c = 0; c < 64; c++) {
        const uint32_t cur = sb + (uint32_t)((c & 1) * STAGE);
        uint8_t* nxt = smd + ((c + 1) & 1) * STAGE;
        const bool pf = (c < 63);
        const int j0n = (c + 1) * 32;

        // (a) issue next chunk's global loads
        float2 adjv[4];
        uint4 bh2[2], bl2[2];
        float q0 = 0.f, q1 = 0.f, r0 = 0.f, r1 = 0.f;
        if (pf) {
            q0 = qb[j0n + jj]; q1 = qb[j0n + jj + 1];
            r0 = rb[j0n + jj]; r1 = rb[j0n + jj + 1];
            #pragma unroll
            for (int g = 0; g < 4; g++)
                adjv[g] = *(const float2*)(adj + (size_t)(i0 + ib + g * 16) * NN + j0n + jj);
            const uint4* srch = (const uint4*)(hi_b + (size_t)(j0n >> 5) * 4096);
            const uint4* srcl = (const uint4*)(lo_b + (size_t)(j0n >> 5) * 4096);
            bh2[0] = srch[tid]; bh2[1] = srch[tid + 256];
            bl2[0] = srcl[tid]; bl2[1] = srcl[tid + 256];
        }

        // (b) MMA on current stage
        mma_chunk2<2>(acc, cur, cur + ASZ, cur + ASZ + TILEB, wr, wc, lane);

        // (c) convert + store next stage
        if (pf) {
            #pragma unroll
            for (int g = 0; g < 4; g++) {
                int i = ib + g * 16;
                float f0 = adjv[g].x * (kv[g] + q0); f0 = fmaxf(f0, 0.01f * f0);
                float f1 = adjv[g].y * (kv[g] + q1); f1 = fmaxf(f1, 0.01f * f1);
                *(uint32_t*)(nxt + i * PITCHB + jj * 2) = pack2h(__expf(f0) * r0, __expf(f1) * r1);
            }
            #pragma unroll
            for (int g = 0; g < 2; g++) {
                int idx = tid + g * 256;
                int d = idx >> 2, seg = idx & 3;
                *(uint4*)(nxt + ASZ + d * PITCHB + seg * 16) = bh2[g];
                *(uint4*)(nxt + ASZ + TILEB + d * PITCHB + seg * 16) = bl2[g];
            }
        }
        __syncthreads();
    }

    // epilogue
    #pragma unroll
    for (int it = 0; it < 2; it++) {
        int r = i0 + wr * 32 + it * 16 + (lane >> 2);
        #pragma unroll
        for (int nt = 0; nt < 4; nt++) {
            int c = wc * 32 + nt * 8 + (lane & 3) * 2;
            float* a = acc[it * 4 + nt];
            *(float2*)(out + ((size_t)b * NN + r) * DD + c)     = make_float2(a[0], a[1]);
            *(float2*)(out + ((size_t)b * NN + r + 8) * DD + c) = make_float2(a[2], a[3]);
        }
    }
}

// ---------------------------------------------------------------------------
extern "C" void kernel_launch(void* const* d_in, const int* in_sizes, int n_in,
                              void* d_out, int out_size)
{
    (void)in_sizes; (void)n_in; (void)out_size;
    const float* x     = (const float*)d_in[0];
    const float* adj   = (const float*)d_in[1];
    const float* W_emb = (const float*)d_in[2];
    const float* b_emb = (const float*)d_in[3];
    const float* w_q   = (const float*)d_in[4];
    const float* b_q   = (const float*)d_in[5];
    const float* w_k   = (const float*)d_in[6];
    const float* b_k   = (const float*)d_in[7];
    float* out = (float*)d_out;

    static bool attr_set = false;
    if (!attr_set) {
        cudaFuncSetAttribute(k_attn, cudaFuncAttributeMaxDynamicSharedMemorySize, 2 * STAGE);
        attr_set = true;
    }

    k_emb<<<(BB * NN) / 128, 256>>>(x, W_emb, b_emb, w_q, b_q, w_k, b_k);
    k_denom<<<dim3(NN / 128, BB, 8), 128>>>(adj);
    k_rcp<<<BB * NN / 256, 256>>>();
    k_attn<<<dim3(NN / 64, BB), 256, 2 * STAGE>>>(adj, out);
}

// round 7
// speedup vs baseline: 4.1025x; 1.3492x over previous
#include <cuda_runtime.h>
#include <cuda_fp16.h>
#include <cstdint>

#define BB 16
#define NN 2048
#define DD 128

// scratch
__device__ float g_q[BB * NN];
__device__ float g_k[BB * NN];
__device__ float g_rden[BB * NN];
__device__ float g_part[8][BB * NN];
// seq_fts^T single fp16, chunk-contiguous: [b][j/32][d][j%32]
__device__ __half g_F[(size_t)BB * DD * NN];

// ---------------------------------------------------------------------------
// helpers
// ---------------------------------------------------------------------------
__device__ __forceinline__ uint32_t smem_u32(const void* p) {
    uint32_t a;
    asm("{ .reg .u64 t; cvta.to.shared.u64 t, %1; cvt.u32.u64 %0, t; }" : "=r"(a) : "l"(p));
    return a;
}

// pitch: 40 f16 = 80 bytes per 32-elem row (conflict-free for ldmatrix)
#define PITCHB 80
#define TILEB  (128 * PITCHB)   // 10240 bytes (128-row operand)
#define ASZ    (64 * PITCHB)    // 5120 bytes (64-row A operand)
#define STAGE  (ASZ + TILEB)    // A + B = 15360

__device__ __forceinline__ void ldmA4(uint32_t base, int lane, uint32_t* a) {
    uint32_t addr = base + (uint32_t)((lane & 15) * PITCHB) + (uint32_t)(((lane >> 4) & 1) << 4);
    asm volatile("ldmatrix.sync.aligned.m8n8.x4.shared.b16 {%0,%1,%2,%3}, [%4];"
                 : "=r"(a[0]), "=r"(a[1]), "=r"(a[2]), "=r"(a[3]) : "r"(addr));
}
__device__ __forceinline__ void ldmB4(uint32_t base, int lane, uint32_t* r) {
    uint32_t addr = base + (uint32_t)(((lane & 7) + ((lane >> 4) << 3)) * PITCHB)
                         + (uint32_t)(((lane >> 3) & 1) << 4);
    asm volatile("ldmatrix.sync.aligned.m8n8.x4.shared.b16 {%0,%1,%2,%3}, [%4];"
                 : "=r"(r[0]), "=r"(r[1]), "=r"(r[2]), "=r"(r[3]) : "r"(addr));
}
__device__ __forceinline__ void mma16816h(float* d, const uint32_t* a, uint32_t b0, uint32_t b1) {
    asm volatile(
        "mma.sync.aligned.m16n8k16.row.col.f32.f16.f16.f32 "
        "{%0,%1,%2,%3}, {%4,%5,%6,%7}, {%8,%9}, {%0,%1,%2,%3};"
        : "+f"(d[0]), "+f"(d[1]), "+f"(d[2]), "+f"(d[3])
        : "r"(a[0]), "r"(a[1]), "r"(a[2]), "r"(a[3]), "r"(b0), "r"(b1));
}

__device__ __forceinline__ void split2h(float v0, float v1, uint32_t& hw, uint32_t& lw) {
    __half h0 = __float2half_rn(v0);
    __half h1 = __float2half_rn(v1);
    __half2 hh; hh.x = h0; hh.y = h1;
    __half2 ll;
    ll.x = __float2half_rn(v0 - __half2float(h0));
    ll.y = __float2half_rn(v1 - __half2float(h1));
    hw = *(uint32_t*)&hh;
    lw = *(uint32_t*)&ll;
}
__device__ __forceinline__ uint32_t pack2h(float v0, float v1) {
    __half2 hh; hh.x = __float2half_rn(v0); hh.y = __float2half_rn(v1);
    return *(uint32_t*)&hh;
}

// 3-term split mainloop (k_emb)
template <int NIT>
__device__ __forceinline__ void mma_chunk3(float (*acc)[4],
                                           uint32_t sAH, uint32_t sAL,
                                           uint32_t sBH, uint32_t sBL,
                                           int wr, int wc, int lane) {
    #pragma unroll
    for (int ks = 0; ks < 2; ks++) {
        uint32_t bh[8], bl[8];
        #pragma unroll
        for (int ntp = 0; ntp < 2; ntp++) {
            uint32_t boff = (uint32_t)((wc * 32 + ntp * 16) * PITCHB + ks * 32);
            ldmB4(sBH + boff, lane, bh + ntp * 4);
            ldmB4(sBL + boff, lane, bl + ntp * 4);
        }
        #pragma unroll
        for (int it = 0; it < NIT; it++) {
            uint32_t aoff = (uint32_t)(((wr * NIT + it) * 16) * PITCHB + ks * 32);
            uint32_t ah[4], al[4];
            ldmA4(sAH + aoff, lane, ah);
            ldmA4(sAL + aoff, lane, al);
            #pragma unroll
            for (int nt = 0; nt < 4; nt++) {
                mma16816h(acc[it * 4 + nt], ah, bh[nt * 2], bh[nt * 2 + 1]);
                mma16816h(acc[it * 4 + nt], ah, bl[nt * 2], bl[nt * 2 + 1]);
                mma16816h(acc[it * 4 + nt], al, bh[nt * 2], bh[nt * 2 + 1]);
            }
        }
    }
}

// single-term mainloop (k_attn): A fp16 x B fp16
template <int NIT>
__device__ __forceinline__ void mma_chunk1(float (*acc)[4],
                                           uint32_t sA, uint32_t sB,
                                           int wr, int wc, int lane) {
    #pragma unroll
    for (int ks = 0; ks < 2; ks++) {
        uint32_t bf[8];
        #pragma unroll
        for (int ntp = 0; ntp < 2; ntp++) {
            uint32_t boff = (uint32_t)((wc * 32 + ntp * 16) * PITCHB + ks * 32);
            ldmB4(sB + boff, lane, bf + ntp * 4);
        }
        #pragma unroll
        for (int it = 0; it < NIT; it++) {
            uint32_t aoff = (uint32_t)(((wr * NIT + it) * 16) * PITCHB + ks * 32);
            uint32_t ah[4];
            ldmA4(sA + aoff, lane, ah);
            #pragma unroll
            for (int nt = 0; nt < 4; nt++)
                mma16816h(acc[it * 4 + nt], ah, bf[nt * 2], bf[nt * 2 + 1]);
        }
    }
}

// ---------------------------------------------------------------------------
// Kernel 1: seq_fts = x @ W^T + b_emb via fp16-split mma.sync.
// Emits q,k scalars and seq_fts^T as single fp16.
// ---------------------------------------------------------------------------
__global__ __launch_bounds__(256) void k_emb(
    const float* __restrict__ x, const float* __restrict__ W,
    const float* __restrict__ b_emb,
    const float* __restrict__ w_q, const float* __restrict__ b_q,
    const float* __restrict__ w_k, const float* __restrict__ b_k)
{
    __shared__ __align__(16) uint8_t sm[4 * TILEB];
    __shared__ float qred[128], kred[128];

    const int tid  = threadIdx.x;
    const int lane = tid & 31;
    const int wid  = tid >> 5;
    const int wr   = wid >> 2;
    const int wc   = wid & 3;
    const int blk  = blockIdx.x;
    const size_t row0 = (size_t)blk * 128;

    if (tid < 128) { qred[tid] = 0.f; kred[tid] = 0.f; }

    const uint32_t sb  = smem_u32(sm);
    const uint32_t sAH = sb, sAL = sb + TILEB, sBH = sb + 2 * TILEB, sBL = sb + 3 * TILEB;

    float acc[16][4];
    #pragma unroll
    for (int i = 0; i < 16; i++)
        #pragma unroll
        for (int j = 0; j < 4; j++) acc[i][j] = 0.f;

    const int jj = (tid & 15) * 2;
    const int rb = tid >> 4;

    for (int k0 = 0; k0 < DD; k0 += 32) {
        __syncthreads();
        #pragma unroll
        for (int g = 0; g < 8; g++) {
            int r = rb + g * 16;
            float2 xv = *(const float2*)(x + (row0 + r) * DD + k0 + jj);
            float2 wv = *(const float2*)(W + (size_t)r * DD + k0 + jj);
            uint32_t hw, lw;
            split2h(xv.x, xv.y, hw, lw);
            *(uint32_t*)(sm + (size_t)0 * TILEB + r * PITCHB + jj * 2) = hw;
            *(uint32_t*)(sm + (size_t)1 * TILEB + r * PITCHB + jj * 2) = lw;
            split2h(wv.x, wv.y, hw, lw);
            *(uint32_t*)(sm + (size_t)2 * TILEB + r * PITCHB + jj * 2) = hw;
            *(uint32_t*)(sm + (size_t)3 * TILEB + r * PITCHB + jj * 2) = lw;
        }
        __syncthreads();
        mma_chunk3<4>(acc, sAH, sAL, sBH, sBL, wr, wc, lane);
    }

    float2 be[4], wq2[4], wk2[4];
    #pragma unroll
    for (int nt = 0; nt < 4; nt++) {
        int c = wc * 32 + nt * 8 + (lane & 3) * 2;
        be[nt]  = *(const float2*)(b_emb + c);
        wq2[nt] = *(const float2*)(w_q + c);
        wk2[nt] = *(const float2*)(w_k + c);
    }
    __syncthreads();

    #pragma unroll
    for (int it = 0; it < 4; it++) {
        float q0 = 0.f, q8 = 0.f, kk0 = 0.f, kk8 = 0.f;
        #pragma unroll
        for (int nt = 0; nt < 4; nt++) {
            float* a = acc[it * 4 + nt];
            a[0] += be[nt].x; a[1] += be[nt].y;
            a[2] += be[nt].x; a[3] += be[nt].y;
            q0 += a[0] * wq2[nt].x + a[1] * wq2[nt].y;
            q8 += a[2] * wq2[nt].x + a[3] * wq2[nt].y;
            kk0 += a[0] * wk2[nt].x + a[1] * wk2[nt].y;
            kk8 += a[2] * wk2[nt].x + a[3] * wk2[nt].y;
        }
        #pragma unroll
        for (int off = 1; off <= 2; off <<= 1) {
            q0 += __shfl_xor_sync(0xffffffffu, q0, off);
            q8 += __shfl_xor_sync(0xffffffffu, q8, off);
            kk0 += __shfl_xor_sync(0xffffffffu, kk0, off);
            kk8 += __shfl_xor_sync(0xffffffffu, kk8, off);
        }
        if ((lane & 3) == 0) {
            int r = wr * 64 + it * 16 + (lane >> 2);
            atomicAdd(&qred[r], q0);
            atomicAdd(&qred[r + 8], q8);
            atomicAdd(&kred[r], kk0);
            atomicAdd(&kred[r + 8], kk8);
        }
    }

    // ---- transpose + store single fp16 ----
    __half* T = (__half*)sm;
    const int b64 = (blk >> 4) * 64;
    const int jc0 = (blk & 15) * 4;

    __syncthreads();
    #pragma unroll
    for (int it = 0; it < 4; it++) {
        int r = wr * 64 + it * 16 + (lane >> 2);
        #pragma unroll
        for (int nt = 0; nt < 4; nt++) {
            int c = wc * 32 + nt * 8 + (lane & 3) * 2;
            float* a = acc[it * 4 + nt];
            #pragma unroll
            for (int u = 0; u < 4; u++)
                T[(c + (u & 1)) * 136 + r + (u >> 1) * 8] = __float2half_rn(a[u]);
        }
    }
    __syncthreads();
    #pragma unroll
    for (int g = 0; g < 8; g++) {
        int lin = tid + g * 256;
        int d   = lin >> 4;
        int seg = lin & 15;
        uint4 v = *(const uint4*)((const uint8_t*)T + d * 272 + seg * 16);
        size_t dst = (((size_t)(b64 + jc0 + (seg >> 2)) * 128 + d) * 32) + (seg & 3) * 8;
        *(uint4*)(g_F + dst) = v;
    }

    __syncthreads();
    if (tid < 128) {
        g_q[row0 + tid] = qred[tid] + b_q[0];
        g_k[row0 + tid] = kred[tid] + b_k[0];
    }
}

// ---------------------------------------------------------------------------
// Kernel 2a: partial column sums (8-way i-split)
// ---------------------------------------------------------------------------
__global__ __launch_bounds__(128) void k_denom(const float* __restrict__ adj)
{
    const int j  = blockIdx.x * 128 + threadIdx.x;
    const int b  = blockIdx.y;
    const int i0 = blockIdx.z * 256;
    const float qv = g_q[b * NN + j];
    const float* __restrict__ kb = g_k + b * NN;

    float s = 0.f;
    #pragma unroll 8
    for (int i = i0; i < i0 + 256; i++) {
        float a = __ldg(adj + (size_t)i * NN + j);
        float f = a * (kb[i] + qv);
        f = fmaxf(f, 0.01f * f);
        s += __expf(f);
    }
    g_part[blockIdx.z][b * NN + j] = s;
}

__global__ __launch_bounds__(256) void k_rcp()
{
    const int idx = blockIdx.x * 256 + threadIdx.x;
    float s = 0.f;
    #pragma unroll
    for (int p = 0; p < 8; p++) s += g_part[p][idx];
    g_rden[idx] = __frcp_rn(s);
}

// ---------------------------------------------------------------------------
// Kernel 3: pipelined attention GEMM, single fp16 operands (1 MMA per k16).
// Tile 64i x 128d, j-chunk 32, double-buffered.
// ---------------------------------------------------------------------------
__global__ __launch_bounds__(256, 2) void k_attn(const float* __restrict__ adj,
                                                 float* __restrict__ out)
{
    __shared__ __align__(16) uint8_t smd[2 * STAGE];

    const int tid  = threadIdx.x;
    const int lane = tid & 31;
    const int wid  = tid >> 5;
    const int wr   = wid >> 2;
    const int wc   = wid & 3;
    const int b    = blockIdx.y;
    const int i0   = blockIdx.x * 64;

    const uint32_t sb = smem_u32(smd);

    const float* __restrict__ qb = g_q + b * NN;
    const float* __restrict__ kb = g_k + b * NN;
    const float* __restrict__ rb = g_rden + b * NN;
    const __half* __restrict__ Fb = g_F + (size_t)b * DD * NN;

    float acc[8][4];
    #pragma unroll
    for (int i = 0; i < 8; i++)
        #pragma unroll
        for (int j = 0; j < 4; j++) acc[i][j] = 0.f;

    const int jj = (tid & 15) * 2;
    const int ib = tid >> 4;

    float kv[4];
    #pragma unroll
    for (int g = 0; g < 4; g++) kv[g] = kb[i0 + ib + g * 16];

    // ---- prologue: stage chunk 0 ----
    {
        const float q0 = qb[jj], q1 = qb[jj + 1];
        const float r0 = rb[jj], r1 = rb[jj + 1];
        #pragma unroll
        for (int g = 0; g < 4; g++) {
            int i = ib + g * 16;
            float2 a2 = *(const float2*)(adj + (size_t)(i0 + i) * NN + jj);
            float f0 = a2.x * (kv[g] + q0); f0 = fmaxf(f0, 0.01f * f0);
            float f1 = a2.y * (kv[g] + q1); f1 = fmaxf(f1, 0.01f * f1);
            *(uint32_t*)(smd + i * PITCHB + jj * 2) = pack2h(__expf(f0) * r0, __expf(f1) * r1);
        }
        const uint4* src = (const uint4*)Fb;
        #pragma unroll
        for (int g = 0; g < 2; g++) {
            int idx = tid + g * 256;
            int d = idx >> 2, seg = idx & 3;
            *(uint4*)(smd + ASZ + d * PITCHB + seg * 16) = src[idx];
        }
    }
    __syncthreads();

    for (int c = 0; c < 64; c++) {
        const uint32_t cur = sb + (uint32_t)((c & 1) * STAGE);
        uint8_t* nxt = smd + ((c + 1) & 1) * STAGE;
        const bool pf = (c < 63);
        const int j0n = (c + 1) * 32;

        // (a) issue next chunk's global loads
        float2 adjv[4];
        uint4 bf2[2];
        float q0 = 0.f, q1 = 0.f, r0 = 0.f, r1 = 0.f;
        if (pf) {
            q0 = qb[j0n + jj]; q1 = qb[j0n + jj + 1];
            r0 = rb[j0n + jj]; r1 = rb[j0n + jj + 1];
            #pragma unroll
            for (int g = 0; g < 4; g++)
                adjv[g] = *(const float2*)(adj + (size_t)(i0 + ib + g * 16) * NN + j0n + jj);
            const uint4* src = (const uint4*)(Fb + (size_t)(j0n >> 5) * 4096);
            bf2[0] = src[tid]; bf2[1] = src[tid + 256];
        }

        // (b) MMA on current stage
        mma_chunk1<2>(acc, cur, cur + ASZ, wr, wc, lane);

        // (c) convert + store next stage
        if (pf) {
            #pragma unroll
            for (int g = 0; g < 4; g++) {
                int i = ib + g * 16;
                float f0 = adjv[g].x * (kv[g] + q0); f0 = fmaxf(f0, 0.01f * f0);
                float f1 = adjv[g].y * (kv[g] + q1); f1 = fmaxf(f1, 0.01f * f1);
                *(uint32_t*)(nxt + i * PITCHB + jj * 2) = pack2h(__expf(f0) * r0, __expf(f1) * r1);
            }
            #pragma unroll
            for (int g = 0; g < 2; g++) {
                int idx = tid + g * 256;
                int d = idx >> 2, seg = idx & 3;
                *(uint4*)(nxt + ASZ + d * PITCHB + seg * 16) = bf2[g];
            }
        }
        __syncthreads();
    }

    // epilogue
    #pragma unroll
    for (int it = 0; it < 2; it++) {
        int r = i0 + wr * 32 + it * 16 + (lane >> 2);
        #pragma unroll
        for (int nt = 0; nt < 4; nt++) {
            int c = wc * 32 + nt * 8 + (lane & 3) * 2;
            float* a = acc[it * 4 + nt];
            *(float2*)(out + ((size_t)b * NN + r) * DD + c)     = make_float2(a[0], a[1]);
            *(float2*)(out + ((size_t)b * NN + r + 8) * DD + c) = make_float2(a[2], a[3]);
        }
    }
}

// ---------------------------------------------------------------------------
extern "C" void kernel_launch(void* const* d_in, const int* in_sizes, int n_in,
                              void* d_out, int out_size)
{
    (void)in_sizes; (void)n_in; (void)out_size;
    const float* x     = (const float*)d_in[0];
    const float* adj   = (const float*)d_in[1];
    const float* W_emb = (const float*)d_in[2];
    const float* b_emb = (const float*)d_in[3];
    const float* w_q   = (const float*)d_in[4];
    const float* b_q   = (const float*)d_in[5];
    const float* w_k   = (const float*)d_in[6];
    const float* b_k   = (const float*)d_in[7];
    float* out = (float*)d_out;

    k_emb<<<(BB * NN) / 128, 256>>>(x, W_emb, b_emb, w_q, b_q, w_k, b_k);
    k_denom<<<dim3(NN / 128, BB, 8), 128>>>(adj);
    k_rcp<<<BB * NN / 256, 256>>>();
    k_attn<<<dim3(NN / 64, BB), 256>>>(adj, out);
}